// round 16
// baseline (speedup 1.0000x reference)
#include <cuda_runtime.h>
#include <cuda_bf16.h>
#include <cuda_fp16.h>
#include <math.h>
#include <stdint.h>

// ---------------- problem constants ----------------
#define NB    4
#define SS    1024
#define EE    2048
#define NH    16
#define NTOK  (NB*SS)          // 4096
#define QKVN  (3*EE)           // 6144
#define NEXP  8
#define EXPH  1024
#define CAP   NTOK
#define NEGV  (-10000.0f)

// weight sizes (floats)
#define NQKVW 12582912
#define NOUTW 4194304
#define NW1   16777216
#define NW2   16777216
#define RESTF4 ((NOUTW+NW1+NW2)/4)
#define QKVF4  (NQKVW/4)

typedef __nv_bfloat16 bf16;

// ---------------- PTX helpers (plain sm_103-safe) ----------------
__device__ __forceinline__ uint32_t smem_to_u32(const void* p) {
    uint32_t a;
    asm("{ .reg .u64 t; cvta.to.shared.u64 t, %1; cvt.u32.u64 %0, t; }" : "=r"(a) : "l"(p));
    return a;
}
__device__ __forceinline__ void cp16(uint32_t dst, const void* src) {
    asm volatile("cp.async.cg.shared.global [%0], [%1], 16;" :: "r"(dst), "l"(src));
}
#define CP_COMMIT()  asm volatile("cp.async.commit_group;" ::: "memory")
#define CP_WAIT(n)   asm volatile("cp.async.wait_group %0;" :: "n"(n) : "memory")

#define LDSM4(r0, r1, r2, r3, addr) \
    asm volatile("ldmatrix.sync.aligned.m8n8.x4.shared.b16 {%0,%1,%2,%3}, [%4];" \
                 : "=r"(r0), "=r"(r1), "=r"(r2), "=r"(r3) : "r"(addr))
#define LDSM4T(r0, r1, r2, r3, addr) \
    asm volatile("ldmatrix.sync.aligned.m8n8.x4.trans.shared.b16 {%0,%1,%2,%3}, [%4];" \
                 : "=r"(r0), "=r"(r1), "=r"(r2), "=r"(r3) : "r"(addr))

#define MMA16816(d, a, b) \
    asm volatile("mma.sync.aligned.m16n8k16.row.col.f32.bf16.bf16.f32 " \
                 "{%0,%1,%2,%3}, {%4,%5,%6,%7}, {%8,%9}, {%0,%1,%2,%3};" \
                 : "+f"((d)[0]), "+f"((d)[1]), "+f"((d)[2]), "+f"((d)[3]) \
                 : "r"((a)[0]), "r"((a)[1]), "r"((a)[2]), "r"((a)[3]), \
                   "r"((b)[0]), "r"((b)[1]))

#define MMAF16(d, a, b) \
    asm volatile("mma.sync.aligned.m16n8k16.row.col.f32.f16.f16.f32 " \
                 "{%0,%1,%2,%3}, {%4,%5,%6,%7}, {%8,%9}, {%0,%1,%2,%3};" \
                 : "+f"((d)[0]), "+f"((d)[1]), "+f"((d)[2]), "+f"((d)[3]) \
                 : "r"((a)[0]), "r"((a)[1]), "r"((a)[2]), "r"((a)[3]), \
                   "r"((b)[0]), "r"((b)[1]))

__device__ __forceinline__ void red_add_v2(float* p, float x, float y) {
    asm volatile("red.global.add.v2.f32 [%0], {%1, %2};" :: "l"(p), "f"(x), "f"(y) : "memory");
}
__device__ __forceinline__ uint32_t pack_bf16x2(float lo, float hi) {
    __nv_bfloat162 t = __floats2bfloat162_rn(lo, hi);
    return *(uint32_t*)&t;
}
__device__ __forceinline__ uint32_t pack_half2(float lo, float hi) {
    __half2 t = __floats2half2_rn(lo, hi);
    return *(uint32_t*)&t;
}

// ---------------- device scratch ----------------
__device__ bf16  g_h_hi [(size_t)NTOK*EE],  g_h_lo [(size_t)NTOK*EE];
__device__ bf16  g_qkvh [(size_t)NTOK*QKVN], g_qkvl[(size_t)NTOK*QKVN];
__device__ bf16  g_at_hi[(size_t)NTOK*EE],  g_at_lo[(size_t)NTOK*EE];
__device__ __half g_h2s [(size_t)NTOK*EE];
__device__ __half g_hx  [(size_t)NEXP*CAP*EXPH];
__device__ bf16  g_qw_hi[(size_t)NQKVW],  g_qw_lo[(size_t)NQKVW];
__device__ bf16  g_ow_hi[(size_t)NOUTW],  g_ow_lo[(size_t)NOUTW];
__device__ __half g_w1s[(size_t)NW1];
__device__ __half g_w2s[(size_t)NW2];
__device__ int   g_cnt[NEXP];
__device__ int   g_idx[NEXP*CAP];
__device__ float g_wgt[NEXP*CAP];
__device__ float g_probs[NEXP];

// ---------------- rmsnorm1 + qkvW converter + counter zeroing ----------------
#define QCVB 1024
__global__ __launch_bounds__(256)
void rmsnorm_kernel(const float* __restrict__ x, const float* __restrict__ w,
                    bf16* __restrict__ yhi, bf16* __restrict__ ylo,
                    const float* __restrict__ qkvW) {
    int n = blockIdx.x;
    int tid = threadIdx.x;
    if (n >= NTOK) {
        if (n == NTOK && tid < NEXP) { g_cnt[tid] = 0; g_probs[tid] = 0.f; }
        size_t base = (size_t)(n - NTOK) * (QKVF4 / QCVB);
        #pragma unroll
        for (int j = 0; j < (QKVF4 / QCVB) / 256; j++) {
            size_t q = base + tid + j * 256;
            size_t i = q * 4;
            float4 v = *(const float4*)(qkvW + i);
            uint32_t h0 = pack_bf16x2(v.x, v.y), h1 = pack_bf16x2(v.z, v.w);
            bf16* hp = (bf16*)&h0; bf16* hq = (bf16*)&h1;
            uint32_t l0 = pack_bf16x2(v.x - __bfloat162float(hp[0]), v.y - __bfloat162float(hp[1]));
            uint32_t l1 = pack_bf16x2(v.z - __bfloat162float(hq[0]), v.w - __bfloat162float(hq[1]));
            *(uint2*)(g_qw_hi + i) = make_uint2(h0, h1);
            *(uint2*)(g_qw_lo + i) = make_uint2(l0, l1);
        }
        return;
    }
    const float* xr = x + (size_t)n * EE;
    float s = 0.f;
    for (int k = tid * 4; k < EE; k += 1024) {
        float4 v = *(const float4*)(xr + k);
        s += v.x*v.x + v.y*v.y + v.z*v.z + v.w*v.w;
    }
    __shared__ float red[256];
    red[tid] = s; __syncthreads();
    for (int o = 128; o; o >>= 1) { if (tid < o) red[tid] += red[tid + o]; __syncthreads(); }
    float r = rsqrtf(red[0] * (1.0f / EE) + 1.1920929e-7f);
    for (int k = tid * 4; k < EE; k += 1024) {
        float4 v = *(const float4*)(xr + k);
        float f0 = v.x*r*w[k], f1 = v.y*r*w[k+1], f2 = v.z*r*w[k+2], f3 = v.w*r*w[k+3];
        uint32_t h0 = pack_bf16x2(f0, f1), h1 = pack_bf16x2(f2, f3);
        bf16* hp = (bf16*)&h0; bf16* hq = (bf16*)&h1;
        uint32_t l0 = pack_bf16x2(f0 - __bfloat162float(hp[0]), f1 - __bfloat162float(hp[1]));
        uint32_t l1 = pack_bf16x2(f2 - __bfloat162float(hq[0]), f3 - __bfloat162float(hq[1]));
        *(uint2*)(yhi + (size_t)n*EE + k) = make_uint2(h0, h1);
        *(uint2*)(ylo + (size_t)n*EE + k) = make_uint2(l0, l1);
    }
}

// fused rmsnorm2 + MoE routing (reads x1 values from `out`)
__global__ __launch_bounds__(256)
void rmsnorm_route_kernel(const float* __restrict__ x, const float* __restrict__ w,
                          __half* __restrict__ ys, const float* __restrict__ gw) {
    __shared__ float h2row[EE];
    __shared__ float red[256];
    __shared__ float lg[NEXP];
    int n = blockIdx.x;
    int tid = threadIdx.x;
    const float* xr = x + (size_t)n * EE;
    float s = 0.f;
    for (int k = tid * 4; k < EE; k += 1024) {
        float4 v = *(const float4*)(xr + k);
        s += v.x*v.x + v.y*v.y + v.z*v.z + v.w*v.w;
    }
    red[tid] = s; __syncthreads();
    for (int o = 128; o; o >>= 1) { if (tid < o) red[tid] += red[tid + o]; __syncthreads(); }
    float r = rsqrtf(red[0] * (1.0f / EE) + 1.1920929e-7f);
    for (int k = tid * 4; k < EE; k += 1024) {
        float4 v = *(const float4*)(xr + k);
        float f0 = v.x*r*w[k], f1 = v.y*r*w[k+1], f2 = v.z*r*w[k+2], f3 = v.w*r*w[k+3];
        *(float4*)(h2row + k) = make_float4(f0, f1, f2, f3);
        uint32_t h0 = pack_half2(f0, f1), h1 = pack_half2(f2, f3);
        *(uint2*)(ys + (size_t)n*EE + k) = make_uint2(h0, h1);
    }
    __syncthreads();
    int wg = tid >> 5, lane = tid & 31;
    const float* gr = gw + (size_t)wg * EE;
    float p = 0.f;
    for (int k = lane * 4; k < EE; k += 128) {
        float4 a = *(const float4*)(h2row + k);
        float4 g4 = *(const float4*)(gr + k);
        p += a.x*g4.x + a.y*g4.y + a.z*g4.z + a.w*g4.w;
    }
    for (int o = 16; o; o >>= 1) p += __shfl_xor_sync(0xffffffffu, p, o);
    if (!lane) lg[wg] = p;
    __syncthreads();
    if (tid == 0) {
        float mx = lg[0];
        #pragma unroll
        for (int e2 = 1; e2 < NEXP; e2++) mx = fmaxf(mx, lg[e2]);
        float ge[NEXP]; float sum = 0.f;
        #pragma unroll
        for (int e2 = 0; e2 < NEXP; e2++) { ge[e2] = __expf(lg[e2] - mx); sum += ge[e2]; }
        float inv = 1.f / sum;
        int i1 = 0; float v1 = -1.f;
        #pragma unroll
        for (int e2 = 0; e2 < NEXP; e2++) {
            ge[e2] *= inv;
            atomicAdd(&g_probs[e2], ge[e2]);
            if (ge[e2] > v1) { v1 = ge[e2]; i1 = e2; }
        }
        int i2 = 0; float v2 = -2.f;
        #pragma unroll
        for (int e2 = 0; e2 < NEXP; e2++)
            if (e2 != i1 && ge[e2] > v2) { v2 = ge[e2]; i2 = e2; }
        int s1 = atomicAdd(&g_cnt[i1], 1);
        g_idx[i1 * CAP + s1] = n; g_wgt[i1 * CAP + s1] = v1;
        int s2 = atomicAdd(&g_cnt[i2], 1);
        g_idx[i2 * CAP + s2] = n; g_wgt[i2 * CAP + s2] = v2;
    }
}

// ---------------- 3-pass split-bf16 GEMM (routing-critical path) ----------------
#define ROWB   80
#define MATB   (128*ROWB)
#define BUFB   (4*MATB)
#define GEMM_SMEM (2*BUFB)
#define RCVY  8
#define RCVB  (RCVY*48)

template<int MODE>
__global__ __launch_bounds__(256, 2)
void tc_gemm(const bf16* __restrict__ Ahi, const bf16* __restrict__ Alo,
             const bf16* __restrict__ Bhi, const bf16* __restrict__ Blo,
             float* __restrict__ C, const float* __restrict__ R,
             bf16* __restrict__ Chi, bf16* __restrict__ Clo,
             int M, int N, int K,
             const float* __restrict__ cvtOW, const float* __restrict__ cvtW1,
             const float* __restrict__ cvtW2) {
    extern __shared__ char smem[];
    const uint32_t SM_BUF = smem_to_u32(smem);
    const int tid = threadIdx.x;

    if (MODE == 0 && (int)blockIdx.y >= (M >> 7)) {
        int cb = ((int)blockIdx.y - (M >> 7)) * gridDim.x + blockIdx.x;
        const size_t perblk = RESTF4 / RCVB;
        size_t base = (size_t)cb * perblk;
        for (size_t q = base + tid; q < base + perblk; q += 256) {
            size_t i = q * 4;
            if (i < (size_t)NOUTW) {
                float4 v = *(const float4*)(cvtOW + i);
                uint32_t h0 = pack_bf16x2(v.x, v.y), h1 = pack_bf16x2(v.z, v.w);
                bf16* hp = (bf16*)&h0; bf16* hq = (bf16*)&h1;
                uint32_t l0 = pack_bf16x2(v.x - __bfloat162float(hp[0]), v.y - __bfloat162float(hp[1]));
                uint32_t l1 = pack_bf16x2(v.z - __bfloat162float(hq[0]), v.w - __bfloat162float(hq[1]));
                *(uint2*)(g_ow_hi + i) = make_uint2(h0, h1);
                *(uint2*)(g_ow_lo + i) = make_uint2(l0, l1);
            } else if (i < (size_t)NOUTW + NW1) {
                size_t k = i - NOUTW;
                float4 v = *(const float4*)(cvtW1 + k);
                *(uint2*)(g_w1s + k) = make_uint2(pack_half2(v.x, v.y), pack_half2(v.z, v.w));
            } else {
                size_t k = i - NOUTW - NW1;
                float4 v = *(const float4*)(cvtW2 + k);
                *(uint2*)(g_w2s + k) = make_uint2(pack_half2(v.x, v.y), pack_half2(v.z, v.w));
            }
        }
        return;
    }

    const int m0 = blockIdx.y * 128;
    const int n0 = blockIdx.x * 128;
    const int wid = tid >> 5;
    const int lid = tid & 31;
    const int wm = (wid >> 2) * 64;
    const int wn = (wid & 3) * 32;
    const int NC = K >> 5;

    auto load_chunk = [&](int kc, int bsel) {
        const uint32_t bb = SM_BUF + (uint32_t)bsel * BUFB;
        const int kofs = kc << 5;
        #pragma unroll
        for (int j = 0; j < 8; j++) {
            int idx = tid + 256 * j;
            int mat = idx >> 9;
            int ci  = idx & 511;
            int r   = ci >> 2;
            int c   = ci & 3;
            uint32_t dst = bb + mat * MATB + r * ROWB + c * 16;
            if (mat < 2) {
                const bf16* src = (mat == 0 ? Ahi : Alo) + (size_t)(m0 + r) * K + kofs + c * 8;
                cp16(dst, src);
            } else {
                const bf16* src = (mat == 2 ? Bhi : Blo) + (size_t)(n0 + r) * K + kofs + c * 8;
                cp16(dst, src);
            }
        }
        CP_COMMIT();
    };

    float acc[4][4][4];
    #pragma unroll
    for (int mt = 0; mt < 4; mt++)
        #pragma unroll
        for (int nt = 0; nt < 4; nt++)
            #pragma unroll
            for (int q = 0; q < 4; q++) acc[mt][nt][q] = 0.f;

    const uint32_t aoff = (uint32_t)((lid & 15) * ROWB + (lid >> 4) * 16);
    const uint32_t boff = (uint32_t)((((lid >> 4) << 3) + (lid & 7)) * ROWB + ((lid >> 3) & 1) * 16);

    load_chunk(0, 0);
    for (int kc = 0; kc < NC; kc++) {
        if (kc + 1 < NC) { load_chunk(kc + 1, (kc + 1) & 1); CP_WAIT(1); }
        else             { CP_WAIT(0); }
        __syncthreads();

        const uint32_t bb = SM_BUF + (uint32_t)(kc & 1) * BUFB;
        const uint32_t a_h = bb + wm * ROWB + aoff;
        const uint32_t a_l = a_h + MATB;
        const uint32_t b_h = bb + 2 * MATB + wn * ROWB + boff;
        const uint32_t b_l = b_h + MATB;

        #pragma unroll
        for (int ks = 0; ks < 2; ks++) {
            uint32_t ua[4][4], ub[4][2], vb[4][2];
            #pragma unroll
            for (int mt = 0; mt < 4; mt++)
                LDSM4(ua[mt][0], ua[mt][1], ua[mt][2], ua[mt][3], a_h + mt * (16 * ROWB) + ks * 32);
            #pragma unroll
            for (int bt = 0; bt < 2; bt++) {
                LDSM4(ub[2*bt][0], ub[2*bt][1], ub[2*bt+1][0], ub[2*bt+1][1], b_h + bt * (16 * ROWB) + ks * 32);
                LDSM4(vb[2*bt][0], vb[2*bt][1], vb[2*bt+1][0], vb[2*bt+1][1], b_l + bt * (16 * ROWB) + ks * 32);
            }
            #pragma unroll
            for (int mt = 0; mt < 4; mt++)
                #pragma unroll
                for (int nt = 0; nt < 4; nt++)
                    MMA16816(acc[mt][nt], ua[mt], ub[nt]);
            #pragma unroll
            for (int mt = 0; mt < 4; mt++)
                #pragma unroll
                for (int nt = 0; nt < 4; nt++)
                    MMA16816(acc[mt][nt], ua[mt], vb[nt]);
            #pragma unroll
            for (int mt = 0; mt < 4; mt++)
                LDSM4(ua[mt][0], ua[mt][1], ua[mt][2], ua[mt][3], a_l + mt * (16 * ROWB) + ks * 32);
            #pragma unroll
            for (int mt = 0; mt < 4; mt++)
                #pragma unroll
                for (int nt = 0; nt < 4; nt++)
                    MMA16816(acc[mt][nt], ua[mt], ub[nt]);
        }
        __syncthreads();
    }

    const int rbase = m0 + wm + (lid >> 2);
    const int cbase = n0 + wn + (lid & 3) * 2;
    #pragma unroll
    for (int mt = 0; mt < 4; mt++) {
        #pragma unroll
        for (int half = 0; half < 2; half++) {
            const int row = rbase + mt * 16 + half * 8;
            #pragma unroll
            for (int nt = 0; nt < 4; nt++) {
                const int col = cbase + nt * 8;
                const float d0 = acc[mt][nt][half * 2 + 0];
                const float d1 = acc[mt][nt][half * 2 + 1];
                if (MODE == 0) {
                    uint32_t h = pack_bf16x2(d0, d1);
                    bf16* hp = (bf16*)&h;
                    uint32_t l = pack_bf16x2(d0 - __bfloat162float(hp[0]), d1 - __bfloat162float(hp[1]));
                    *(uint32_t*)(Chi + (size_t)row * N + col) = h;
                    *(uint32_t*)(Clo + (size_t)row * N + col) = l;
                } else {
                    const float* rp = R + (size_t)row * N + col;
                    *(float2*)(C + (size_t)row * N + col) = make_float2(d0 + rp[0], d1 + rp[1]);
                }
            }
        }
    }
}

// ---------------- 1-pass fp16 GEMM (post-routing MoE only) ----------------
#define STG1B  (2*MATB)
#define GEMM1_SMEM (2*STG1B)

template<int MODE>
__global__ __launch_bounds__(256, 2)
void tc_gemm1(const __half* __restrict__ A, const __half* __restrict__ B,
              float* __restrict__ C, __half* __restrict__ Cs,
              int M, int N, int K) {
    extern __shared__ char smem[];
    const uint32_t SM_BUF = smem_to_u32(smem);

    const int e = blockIdx.z;
    const int Me = g_cnt[e];
    const int m0 = blockIdx.y * 128;
    const int n0 = blockIdx.x * 128;
    if (m0 >= Me) return;
    const int tid = threadIdx.x;
    const int wid = tid >> 5;
    const int lid = tid & 31;
    const int wm = (wid >> 2) * 64;
    const int wn = (wid & 3) * 32;

    const size_t bbase = (size_t)e * (size_t)N * K;
    const int NC = K >> 5;

    auto load_chunk = [&](int kc, int bsel) {
        const uint32_t bb = SM_BUF + (uint32_t)bsel * STG1B;
        const int kofs = kc << 5;
        #pragma unroll
        for (int j = 0; j < 4; j++) {
            int idx = tid + 256 * j;
            int mat = idx >> 9;
            int ci  = idx & 511;
            int r   = ci >> 2;
            int c   = ci & 3;
            uint32_t dst = bb + mat * MATB + r * ROWB + c * 16;
            if (mat == 0) {
                int rr = m0 + r; if (rr >= Me) rr = Me - 1;
                int arow = (MODE == 2) ? g_idx[e * CAP + rr] : (e * CAP + rr);
                cp16(dst, A + (size_t)arow * K + kofs + c * 8);
            } else {
                cp16(dst, B + bbase + (size_t)(n0 + r) * K + kofs + c * 8);
            }
        }
        CP_COMMIT();
    };

    float acc[4][4][4];
    #pragma unroll
    for (int mt = 0; mt < 4; mt++)
        #pragma unroll
        for (int nt = 0; nt < 4; nt++)
            #pragma unroll
            for (int q = 0; q < 4; q++) acc[mt][nt][q] = 0.f;

    const uint32_t aoff = (uint32_t)((lid & 15) * ROWB + (lid >> 4) * 16);
    const uint32_t boff = (uint32_t)((((lid >> 4) << 3) + (lid & 7)) * ROWB + ((lid >> 3) & 1) * 16);

    load_chunk(0, 0);
    for (int kc = 0; kc < NC; kc++) {
        if (kc + 1 < NC) { load_chunk(kc + 1, (kc + 1) & 1); CP_WAIT(1); }
        else             { CP_WAIT(0); }
        __syncthreads();

        const uint32_t bb = SM_BUF + (uint32_t)(kc & 1) * STG1B;
        const uint32_t a_s = bb + wm * ROWB + aoff;
        const uint32_t b_s = bb + MATB + wn * ROWB + boff;

        #pragma unroll
        for (int ks = 0; ks < 2; ks++) {
            uint32_t ua[4][4], ub[4][2];
            #pragma unroll
            for (int mt = 0; mt < 4; mt++)
                LDSM4(ua[mt][0], ua[mt][1], ua[mt][2], ua[mt][3], a_s + mt * (16 * ROWB) + ks * 32);
            #pragma unroll
            for (int bt = 0; bt < 2; bt++)
                LDSM4(ub[2*bt][0], ub[2*bt][1], ub[2*bt+1][0], ub[2*bt+1][1], b_s + bt * (16 * ROWB) + ks * 32);
            #pragma unroll
            for (int mt = 0; mt < 4; mt++)
                #pragma unroll
                for (int nt = 0; nt < 4; nt++)
                    MMAF16(acc[mt][nt], ua[mt], ub[nt]);
        }
        __syncthreads();
    }

    const int rbase = m0 + wm + (lid >> 2);
    const int cbase = n0 + wn + (lid & 3) * 2;
    #pragma unroll
    for (int mt = 0; mt < 4; mt++) {
        #pragma unroll
        for (int half = 0; half < 2; half++) {
            const int row = rbase + mt * 16 + half * 8;
            if (row >= Me) continue;
            int tok = 0; float wv = 0.f;
            if (MODE == 3) { tok = g_idx[e * CAP + row]; wv = g_wgt[e * CAP + row]; }
            #pragma unroll
            for (int nt = 0; nt < 4; nt++) {
                const int col = cbase + nt * 8;
                const float d0 = acc[mt][nt][half * 2 + 0];
                const float d1 = acc[mt][nt][half * 2 + 1];
                if (MODE == 2) {
                    float s0 = d0 / (1.f + __expf(-d0));
                    float s1 = d1 / (1.f + __expf(-d1));
                    *(uint32_t*)(Cs + ((size_t)e * CAP + row) * N + col) = pack_half2(s0, s1);
                } else {
                    red_add_v2(C + (size_t)tok * N + col, wv * d0, wv * d1);
                }
            }
        }
    }
}

// ---------------- tensor-core attention v2 ----------------
// CTA: 128 threads (4 warps), q-tile 64 rows, KV tile 32 rows -> 2 CTAs/SM.
#define AROWB 272
#define AKROWS 32
#define AMATB (AKROWS*AROWB)       // 8704
#define ABUFB (4*AMATB)            // 34816
#define ATT_SMEM (2*ABUFB)         // 69632

__global__ __launch_bounds__(128, 2)
void attn_tc_kernel(const bf16* __restrict__ qkvh, const bf16* __restrict__ qkvl,
                    const int* __restrict__ mask,
                    bf16* __restrict__ ohi, bf16* __restrict__ olo) {
    extern __shared__ char asmem[];
    const uint32_t SB = smem_to_u32(asmem);
    const int qt = (int)gridDim.x - 1 - (int)blockIdx.x;  // longest-first, q-tiles of 64
    const int h  = blockIdx.y;
    const int b  = blockIdx.z;
    const int tid = threadIdx.x;
    const int wid = tid >> 5;          // 0..3
    const int lid = tid & 31;
    const int c2  = (lid & 3) * 2;
    const float isc = 0.08838834764831845f;

    const int tqA = qt * 64 + wid * 16 + (lid >> 2);
    const int tqB = tqA + 8;
    const int wrowmin = qt * 64 + wid * 16;
    const int tok = b * SS + h * 64 + (tqA >> 4);
    const size_t qb = (size_t)tok * QKVN;
    const int colA = (tqA & 15) << 7;
    const int colB = (tqB & 15) << 7;

    uint32_t qa_h[8][4], qa_l[8][4];
    #pragma unroll
    for (int ks = 0; ks < 8; ks++) {
        int k0 = ks * 16 + c2;
        qa_h[ks][0] = *(const uint32_t*)(qkvh + qb + colA + k0);
        qa_h[ks][1] = *(const uint32_t*)(qkvh + qb + colB + k0);
        qa_h[ks][2] = *(const uint32_t*)(qkvh + qb + colA + k0 + 8);
        qa_h[ks][3] = *(const uint32_t*)(qkvh + qb + colB + k0 + 8);
        qa_l[ks][0] = *(const uint32_t*)(qkvl + qb + colA + k0);
        qa_l[ks][1] = *(const uint32_t*)(qkvl + qb + colB + k0);
        qa_l[ks][2] = *(const uint32_t*)(qkvl + qb + colA + k0 + 8);
        qa_l[ks][3] = *(const uint32_t*)(qkvl + qb + colB + k0 + 8);
    }

    float o[16][4];
    #pragma unroll
    for (int dt = 0; dt < 16; dt++)
        #pragma unroll
        for (int q = 0; q < 4; q++) o[dt][q] = 0.f;
    float mA = -1e30f, lA = 0.f, mB = -1e30f, lB = 0.f;

    const int KT = 2 * qt + 2;   // KV tiles of 32 covering rows 0..qt*64+63

    auto load_kv = [&](int kt, int bsel) {
        const uint32_t bb = SB + (uint32_t)bsel * ABUFB;
        #pragma unroll
        for (int j = 0; j < 16; j++) {
            int idx = tid + 128 * j;       // 0..2047
            int mat = idx >> 9;            // 0:Kh 1:Kl 2:Vh 3:Vl
            int ci  = idx & 511;
            int r   = ci >> 4;             // 0..31
            int c   = ci & 15;
            int t   = kt * AKROWS + r;
            size_t src = ((size_t)(b * SS + h * 64 + (t >> 4))) * QKVN
                       + ((t & 15) << 7) + ((mat < 2) ? 2048 : 4096) + c * 8;
            const bf16* sp = ((mat & 1) ? qkvl : qkvh) + src;
            cp16(bb + mat * AMATB + r * AROWB + c * 16, sp);
        }
        CP_COMMIT();
    };

    const uint32_t koff = (uint32_t)((((lid >> 4) << 3) + (lid & 7)) * AROWB + ((lid >> 3) & 1) * 16);
    const uint32_t voff = (uint32_t)((((lid >> 3) & 1) * 8 + (lid & 7)) * AROWB + (lid >> 4) * 16);

    load_kv(0, 0);
    for (int kt = 0; kt < KT; kt++) {
        if (kt + 1 < KT) { load_kv(kt + 1, (kt + 1) & 1); CP_WAIT(1); }
        else             { CP_WAIT(0); }
        __syncthreads();
        const uint32_t bb = SB + (uint32_t)(kt & 1) * ABUFB;
        const uint32_t Kh = bb, Kl = bb + AMATB, Vh = bb + 2 * AMATB, Vl = bb + 3 * AMATB;

        // scores: 16 rows x 32 kv
        float s[4][4];
        #pragma unroll
        for (int nt = 0; nt < 4; nt++)
            #pragma unroll
            for (int q = 0; q < 4; q++) s[nt][q] = 0.f;

        #pragma unroll
        for (int ks = 0; ks < 8; ks++) {
            #pragma unroll
            for (int g = 0; g < 2; g++) {
                uint32_t kh[4], kl[4];
                LDSM4(kh[0], kh[1], kh[2], kh[3], Kh + g * (16 * AROWB) + koff + ks * 32);
                LDSM4(kl[0], kl[1], kl[2], kl[3], Kl + g * (16 * AROWB) + koff + ks * 32);
                uint32_t bh0[2] = {kh[0], kh[1]}, bh1[2] = {kh[2], kh[3]};
                uint32_t bl0[2] = {kl[0], kl[1]}, bl1[2] = {kl[2], kl[3]};
                MMA16816(s[2*g],   qa_h[ks], bh0);
                MMA16816(s[2*g+1], qa_h[ks], bh1);
                MMA16816(s[2*g],   qa_h[ks], bl0);
                MMA16816(s[2*g+1], qa_h[ks], bl1);
                MMA16816(s[2*g],   qa_l[ks], bh0);
                MMA16816(s[2*g+1], qa_l[ks], bh1);
            }
        }

        const int tk0 = kt * AKROWS;
        const bool fullcausal = (tk0 + AKROWS - 1) <= wrowmin;
        #pragma unroll
        for (int nt = 0; nt < 4; nt++) {
            int t0 = tk0 + nt * 8 + c2;
            int2 mv = *(const int2*)(mask + b * SS + t0);
            #pragma unroll
            for (int q = 0; q < 4; q++) {
                float v = s[nt][q] * isc;
                if (((q & 1) ? mv.y : mv.x) == 0) v = NEGV;
                if (fullcausal) {
                    v += 1.0f;
                } else {
                    int t = t0 + (q & 1);
                    int row = (q < 2) ? tqA : tqB;
                    v += (t <= row) ? 1.0f : NEGV;
                }
                s[nt][q] = v;
            }
        }

        float mxA = -1e30f, mxB = -1e30f;
        #pragma unroll
        for (int nt = 0; nt < 4; nt++) {
            mxA = fmaxf(mxA, fmaxf(s[nt][0], s[nt][1]));
            mxB = fmaxf(mxB, fmaxf(s[nt][2], s[nt][3]));
        }
        mxA = fmaxf(mxA, __shfl_xor_sync(0xffffffffu, mxA, 1));
        mxA = fmaxf(mxA, __shfl_xor_sync(0xffffffffu, mxA, 2));
        mxB = fmaxf(mxB, __shfl_xor_sync(0xffffffffu, mxB, 1));
        mxB = fmaxf(mxB, __shfl_xor_sync(0xffffffffu, mxB, 2));
        float mnA = fmaxf(mA, mxA), mnB = fmaxf(mB, mxB);
        float sumA = 0.f, sumB = 0.f;
        #pragma unroll
        for (int nt = 0; nt < 4; nt++) {
            s[nt][0] = __expf(s[nt][0] - mnA);
            s[nt][1] = __expf(s[nt][1] - mnA);
            s[nt][2] = __expf(s[nt][2] - mnB);
            s[nt][3] = __expf(s[nt][3] - mnB);
            sumA += s[nt][0] + s[nt][1];
            sumB += s[nt][2] + s[nt][3];
        }
        sumA += __shfl_xor_sync(0xffffffffu, sumA, 1);
        sumA += __shfl_xor_sync(0xffffffffu, sumA, 2);
        sumB += __shfl_xor_sync(0xffffffffu, sumB, 1);
        sumB += __shfl_xor_sync(0xffffffffu, sumB, 2);
        float aA = __expf(mA - mnA), aB = __expf(mB - mnB);
        lA = lA * aA + sumA;  mA = mnA;
        lB = lB * aB + sumB;  mB = mnB;
        #pragma unroll
        for (int dt = 0; dt < 16; dt++) {
            o[dt][0] *= aA; o[dt][1] *= aA;
            o[dt][2] *= aB; o[dt][3] *= aB;
        }

        // O += P V  (P: 16x32, V: 32x128)
        #pragma unroll
        for (int ks2 = 0; ks2 < 2; ks2++) {
            uint32_t pa_h[4], pa_l[4];
            {
                float* p0 = s[2*ks2]; float* p1 = s[2*ks2+1];
                pa_h[0] = pack_bf16x2(p0[0], p0[1]);
                pa_h[1] = pack_bf16x2(p0[2], p0[3]);
                pa_h[2] = pack_bf16x2(p1[0], p1[1]);
                pa_h[3] = pack_bf16x2(p1[2], p1[3]);
                bf16* t0 = (bf16*)&pa_h[0]; bf16* t1 = (bf16*)&pa_h[1];
                bf16* t2 = (bf16*)&pa_h[2]; bf16* t3 = (bf16*)&pa_h[3];
                pa_l[0] = pack_bf16x2(p0[0]-__bfloat162float(t0[0]), p0[1]-__bfloat162float(t0[1]));
                pa_l[1] = pack_bf16x2(p0[2]-__bfloat162float(t1[0]), p0[3]-__bfloat162float(t1[1]));
                pa_l[2] = pack_bf16x2(p1[0]-__bfloat162float(t2[0]), p1[1]-__bfloat162float(t2[1]));
                pa_l[3] = pack_bf16x2(p1[2]-__bfloat162float(t3[0]), p1[3]-__bfloat162float(t3[1]));
            }
            #pragma unroll
            for (int db = 0; db < 8; db++) {
                uint32_t vh[4], vl[4];
                LDSM4T(vh[0], vh[1], vh[2], vh[3], Vh + ks2 * (16 * AROWB) + db * 32 + voff);
                LDSM4T(vl[0], vl[1], vl[2], vl[3], Vl + ks2 * (16 * AROWB) + db * 32 + voff);
                uint32_t bh0[2] = {vh[0], vh[1]}, bh1[2] = {vh[2], vh[3]};
                uint32_t bl0[2] = {vl[0], vl[1]}, bl1[2] = {vl[2], vl[3]};
                MMA16816(o[2*db],   pa_h, bh0);
                MMA16816(o[2*db+1], pa_h, bh1);
                MMA16816(o[2*db],   pa_h, bl0);
                MMA16816(o[2*db+1], pa_h, bl1);
                MMA16816(o[2*db],   pa_l, bh0);
                MMA16816(o[2*db+1], pa_l, bh1);
            }
        }
        __syncthreads();
    }

    const float ivA = 1.f / lA, ivB = 1.f / lB;
    const size_t obase = (size_t)tok * EE;
    #pragma unroll
    for (int dt = 0; dt < 16; dt++) {
        int d = dt * 8 + c2;
        float a0 = o[dt][0] * ivA, a1 = o[dt][1] * ivA;
        float b0 = o[dt][2] * ivB, b1 = o[dt][3] * ivB;
        uint32_t hA = pack_bf16x2(a0, a1);
        bf16* tp = (bf16*)&hA;
        uint32_t lA2 = pack_bf16x2(a0 - __bfloat162float(tp[0]), a1 - __bfloat162float(tp[1]));
        *(uint32_t*)(ohi + obase + colA + d) = hA;
        *(uint32_t*)(olo + obase + colA + d) = lA2;
        uint32_t hB = pack_bf16x2(b0, b1);
        bf16* tq2 = (bf16*)&hB;
        uint32_t lB2 = pack_bf16x2(b0 - __bfloat162float(tq2[0]), b1 - __bfloat162float(tq2[1]));
        *(uint32_t*)(ohi + obase + colB + d) = hB;
        *(uint32_t*)(olo + obase + colB + d) = lB2;
    }
}

__global__ void loss_kernel(float* __restrict__ out, int lossidx) {
    if (threadIdx.x == 0) {
        float pr[NEXP]; float mean = 0.f;
        #pragma unroll
        for (int e = 0; e < NEXP; e++) { pr[e] = g_probs[e] * (1.0f / NTOK); mean += pr[e]; }
        mean *= (1.0f / NEXP);
        float var = 0.f;
        #pragma unroll
        for (int e = 0; e < NEXP; e++) { float d = pr[e] - mean; var += d * d; }
        var *= (1.0f / NEXP);
        out[lossidx] = var / (mean * mean + 1e-10f);
    }
}

// ---------------- launch ----------------
extern "C" void kernel_launch(void* const* d_in, const int* in_sizes, int n_in,
                              void* d_out, int out_size) {
    const float* x     = (const float*)d_in[0];
    const int*   mask  = (const int*)  d_in[1];
    const float* n1w   = (const float*)d_in[2];
    const float* qkvW  = (const float*)d_in[3];
    const float* outW  = (const float*)d_in[4];
    const float* n2w   = (const float*)d_in[5];
    const float* gateW = (const float*)d_in[6];
    const float* W1    = (const float*)d_in[7];
    const float* W2    = (const float*)d_in[8];
    float* out = (float*)d_out;

    bf16 *phh, *phl, *pqvh, *pqvl, *path, *patl;
    __half *ph2s, *phx, *pw1s, *pw2s;
    bf16 *pqwh, *pqwl, *powh, *powl;
    cudaGetSymbolAddress((void**)&phh,  g_h_hi);  cudaGetSymbolAddress((void**)&phl,  g_h_lo);
    cudaGetSymbolAddress((void**)&pqvh, g_qkvh);  cudaGetSymbolAddress((void**)&pqvl, g_qkvl);
    cudaGetSymbolAddress((void**)&path, g_at_hi); cudaGetSymbolAddress((void**)&patl, g_at_lo);
    cudaGetSymbolAddress((void**)&ph2s, g_h2s);
    cudaGetSymbolAddress((void**)&phx,  g_hx);
    cudaGetSymbolAddress((void**)&pqwh, g_qw_hi); cudaGetSymbolAddress((void**)&pqwl, g_qw_lo);
    cudaGetSymbolAddress((void**)&powh, g_ow_hi); cudaGetSymbolAddress((void**)&powl, g_ow_lo);
    cudaGetSymbolAddress((void**)&pw1s, g_w1s);
    cudaGetSymbolAddress((void**)&pw2s, g_w2s);

    cudaFuncSetAttribute(tc_gemm<0>, cudaFuncAttributeMaxDynamicSharedMemorySize, GEMM_SMEM);
    cudaFuncSetAttribute(tc_gemm<1>, cudaFuncAttributeMaxDynamicSharedMemorySize, GEMM_SMEM);
    cudaFuncSetAttribute(tc_gemm1<2>, cudaFuncAttributeMaxDynamicSharedMemorySize, GEMM1_SMEM);
    cudaFuncSetAttribute(tc_gemm1<3>, cudaFuncAttributeMaxDynamicSharedMemorySize, GEMM1_SMEM);
    cudaFuncSetAttribute(attn_tc_kernel, cudaFuncAttributeMaxDynamicSharedMemorySize, ATT_SMEM);

    rmsnorm_kernel<<<NTOK + QCVB, 256>>>(x, n1w, phh, phl, qkvW);
    tc_gemm<0><<<dim3(QKVN / 128, NTOK / 128 + RCVY), 256, GEMM_SMEM>>>(
        phh, phl, pqwh, pqwl, nullptr, nullptr, pqvh, pqvl,
        NTOK, QKVN, EE, outW, W1, W2);
    attn_tc_kernel<<<dim3(SS / 64, NH, NB), 128, ATT_SMEM>>>(pqvh, pqvl, mask, path, patl);
    tc_gemm<1><<<dim3(EE / 128, NTOK / 128), 256, GEMM_SMEM>>>(
        path, patl, powh, powl, out, x, nullptr, nullptr,
        NTOK, EE, EE, nullptr, nullptr, nullptr);
    rmsnorm_route_kernel<<<NTOK, 256>>>(out, n2w, ph2s, gateW);
    if (out_size > NTOK * EE)
        loss_kernel<<<1, 32>>>(out, out_size - 1);
    tc_gemm1<2><<<dim3(EXPH / 128, CAP / 128, NEXP), 256, GEMM1_SMEM>>>(
        ph2s, pw1s, nullptr, phx, CAP, EXPH, EE);
    tc_gemm1<3><<<dim3(EE / 128, CAP / 128, NEXP), 256, GEMM1_SMEM>>>(
        phx, pw2s, out, nullptr, CAP, EE, EXPH);
}

// round 17
// speedup vs baseline: 1.0154x; 1.0154x over previous
#include <cuda_runtime.h>
#include <cuda_bf16.h>
#include <cuda_fp16.h>
#include <math.h>
#include <stdint.h>

// ---------------- problem constants ----------------
#define NB    4
#define SS    1024
#define EE    2048
#define NH    16
#define NTOK  (NB*SS)          // 4096
#define QKVN  (3*EE)           // 6144
#define NEXP  8
#define EXPH  1024
#define CAP   NTOK
#define NEGV  (-10000.0f)

// weight sizes (floats)
#define NQKVW 12582912
#define NOUTW 4194304
#define NW1   16777216
#define NW2   16777216
#define RESTF4 ((NOUTW+NW1+NW2)/4)
#define QKVF4  (NQKVW/4)

typedef __nv_bfloat16 bf16;

// ---------------- PTX helpers (plain sm_103-safe) ----------------
__device__ __forceinline__ uint32_t smem_to_u32(const void* p) {
    uint32_t a;
    asm("{ .reg .u64 t; cvta.to.shared.u64 t, %1; cvt.u32.u64 %0, t; }" : "=r"(a) : "l"(p));
    return a;
}
__device__ __forceinline__ void cp16(uint32_t dst, const void* src) {
    asm volatile("cp.async.cg.shared.global [%0], [%1], 16;" :: "r"(dst), "l"(src));
}
#define CP_COMMIT()  asm volatile("cp.async.commit_group;" ::: "memory")
#define CP_WAIT(n)   asm volatile("cp.async.wait_group %0;" :: "n"(n) : "memory")

#define LDSM4(r0, r1, r2, r3, addr) \
    asm volatile("ldmatrix.sync.aligned.m8n8.x4.shared.b16 {%0,%1,%2,%3}, [%4];" \
                 : "=r"(r0), "=r"(r1), "=r"(r2), "=r"(r3) : "r"(addr))
#define LDSM4T(r0, r1, r2, r3, addr) \
    asm volatile("ldmatrix.sync.aligned.m8n8.x4.trans.shared.b16 {%0,%1,%2,%3}, [%4];" \
                 : "=r"(r0), "=r"(r1), "=r"(r2), "=r"(r3) : "r"(addr))

#define MMA16816(d, a, b) \
    asm volatile("mma.sync.aligned.m16n8k16.row.col.f32.bf16.bf16.f32 " \
                 "{%0,%1,%2,%3}, {%4,%5,%6,%7}, {%8,%9}, {%0,%1,%2,%3};" \
                 : "+f"((d)[0]), "+f"((d)[1]), "+f"((d)[2]), "+f"((d)[3]) \
                 : "r"((a)[0]), "r"((a)[1]), "r"((a)[2]), "r"((a)[3]), \
                   "r"((b)[0]), "r"((b)[1]))

#define MMAF16(d, a, b) \
    asm volatile("mma.sync.aligned.m16n8k16.row.col.f32.f16.f16.f32 " \
                 "{%0,%1,%2,%3}, {%4,%5,%6,%7}, {%8,%9}, {%0,%1,%2,%3};" \
                 : "+f"((d)[0]), "+f"((d)[1]), "+f"((d)[2]), "+f"((d)[3]) \
                 : "r"((a)[0]), "r"((a)[1]), "r"((a)[2]), "r"((a)[3]), \
                   "r"((b)[0]), "r"((b)[1]))

__device__ __forceinline__ void red_add_v2(float* p, float x, float y) {
    asm volatile("red.global.add.v2.f32 [%0], {%1, %2};" :: "l"(p), "f"(x), "f"(y) : "memory");
}
__device__ __forceinline__ uint32_t pack_bf16x2(float lo, float hi) {
    __nv_bfloat162 t = __floats2bfloat162_rn(lo, hi);
    return *(uint32_t*)&t;
}
__device__ __forceinline__ uint32_t pack_half2(float lo, float hi) {
    __half2 t = __floats2half2_rn(lo, hi);
    return *(uint32_t*)&t;
}

// ---------------- device scratch ----------------
__device__ bf16  g_h_hi [(size_t)NTOK*EE],  g_h_lo [(size_t)NTOK*EE];
__device__ bf16  g_qkvh [(size_t)NTOK*QKVN], g_qkvl[(size_t)NTOK*QKVN];
__device__ bf16  g_at_hi[(size_t)NTOK*EE],  g_at_lo[(size_t)NTOK*EE];
__device__ __half g_h2s [(size_t)NTOK*EE];
__device__ __half g_hx  [(size_t)NEXP*CAP*EXPH];
__device__ bf16  g_qw_hi[(size_t)NQKVW],  g_qw_lo[(size_t)NQKVW];
__device__ bf16  g_ow_hi[(size_t)NOUTW],  g_ow_lo[(size_t)NOUTW];
__device__ __half g_w1s[(size_t)NW1];
__device__ __half g_w2s[(size_t)NW2];
__device__ int   g_cnt[NEXP];
__device__ int   g_idx[NEXP*CAP];
__device__ float g_wgt[NEXP*CAP];
__device__ float g_probs[NEXP];
__device__ int   g_obcnt[NTOK/128];     // out-proj m-block completion counters

// ---------------- rmsnorm1 + qkvW converter + counter zeroing ----------------
#define QCVB 1024
__global__ __launch_bounds__(256)
void rmsnorm_kernel(const float* __restrict__ x, const float* __restrict__ w,
                    bf16* __restrict__ yhi, bf16* __restrict__ ylo,
                    const float* __restrict__ qkvW) {
    int n = blockIdx.x;
    int tid = threadIdx.x;
    if (n >= NTOK) {
        if (n == NTOK) {
            if (tid < NEXP) { g_cnt[tid] = 0; g_probs[tid] = 0.f; }
            if (tid >= 32 && tid < 32 + NTOK/128) g_obcnt[tid - 32] = 0;
        }
        size_t base = (size_t)(n - NTOK) * (QKVF4 / QCVB);
        #pragma unroll
        for (int j = 0; j < (QKVF4 / QCVB) / 256; j++) {
            size_t q = base + tid + j * 256;
            size_t i = q * 4;
            float4 v = *(const float4*)(qkvW + i);
            uint32_t h0 = pack_bf16x2(v.x, v.y), h1 = pack_bf16x2(v.z, v.w);
            bf16* hp = (bf16*)&h0; bf16* hq = (bf16*)&h1;
            uint32_t l0 = pack_bf16x2(v.x - __bfloat162float(hp[0]), v.y - __bfloat162float(hp[1]));
            uint32_t l1 = pack_bf16x2(v.z - __bfloat162float(hq[0]), v.w - __bfloat162float(hq[1]));
            *(uint2*)(g_qw_hi + i) = make_uint2(h0, h1);
            *(uint2*)(g_qw_lo + i) = make_uint2(l0, l1);
        }
        return;
    }
    const float* xr = x + (size_t)n * EE;
    float s = 0.f;
    for (int k = tid * 4; k < EE; k += 1024) {
        float4 v = *(const float4*)(xr + k);
        s += v.x*v.x + v.y*v.y + v.z*v.z + v.w*v.w;
    }
    __shared__ float red[256];
    red[tid] = s; __syncthreads();
    for (int o = 128; o; o >>= 1) { if (tid < o) red[tid] += red[tid + o]; __syncthreads(); }
    float r = rsqrtf(red[0] * (1.0f / EE) + 1.1920929e-7f);
    for (int k = tid * 4; k < EE; k += 1024) {
        float4 v = *(const float4*)(xr + k);
        float f0 = v.x*r*w[k], f1 = v.y*r*w[k+1], f2 = v.z*r*w[k+2], f3 = v.w*r*w[k+3];
        uint32_t h0 = pack_bf16x2(f0, f1), h1 = pack_bf16x2(f2, f3);
        bf16* hp = (bf16*)&h0; bf16* hq = (bf16*)&h1;
        uint32_t l0 = pack_bf16x2(f0 - __bfloat162float(hp[0]), f1 - __bfloat162float(hp[1]));
        uint32_t l1 = pack_bf16x2(f2 - __bfloat162float(hq[0]), f3 - __bfloat162float(hq[1]));
        *(uint2*)(yhi + (size_t)n*EE + k) = make_uint2(h0, h1);
        *(uint2*)(ylo + (size_t)n*EE + k) = make_uint2(l0, l1);
    }
}

// ---------------- 3-pass split-bf16 GEMM (routing-critical path) ----------------
// MODE 0: bf16 hi/lo out (QKV); extra grid.y rows run weight converters.
// MODE 1: C = acc + R (out proj, writes x1 into `out`); extra grid.y rows run
//         the fused rmsnorm2+routing consumers, gated on per-m-block counters.
#define ROWB   80
#define MATB   (128*ROWB)
#define BUFB   (4*MATB)
#define GEMM_SMEM (2*BUFB)
#define RCVY  8
#define RCVB  (RCVY*48)
#define ROUTEY 32          // consumer rows appended to out-proj grid.y (32*16=512 blocks)

template<int MODE>
__global__ __launch_bounds__(256, 2)
void tc_gemm(const bf16* __restrict__ Ahi, const bf16* __restrict__ Alo,
             const bf16* __restrict__ Bhi, const bf16* __restrict__ Blo,
             float* __restrict__ C, const float* __restrict__ R,
             bf16* __restrict__ Chi, bf16* __restrict__ Clo,
             int M, int N, int K,
             const float* __restrict__ cvtOW, const float* __restrict__ cvtW1,
             const float* __restrict__ cvtW2,
             const float* __restrict__ gwR, __half* __restrict__ ysR) {
    extern __shared__ char smem[];
    const uint32_t SM_BUF = smem_to_u32(smem);
    const int tid = threadIdx.x;

    if (MODE == 0 && (int)blockIdx.y >= (M >> 7)) {
        // ---- weight converter: outW (bf16 split) + W1/W2 (fp16) ----
        int cb = ((int)blockIdx.y - (M >> 7)) * gridDim.x + blockIdx.x;
        const size_t perblk = RESTF4 / RCVB;
        size_t base = (size_t)cb * perblk;
        for (size_t q = base + tid; q < base + perblk; q += 256) {
            size_t i = q * 4;
            if (i < (size_t)NOUTW) {
                float4 v = *(const float4*)(cvtOW + i);
                uint32_t h0 = pack_bf16x2(v.x, v.y), h1 = pack_bf16x2(v.z, v.w);
                bf16* hp = (bf16*)&h0; bf16* hq = (bf16*)&h1;
                uint32_t l0 = pack_bf16x2(v.x - __bfloat162float(hp[0]), v.y - __bfloat162float(hp[1]));
                uint32_t l1 = pack_bf16x2(v.z - __bfloat162float(hq[0]), v.w - __bfloat162float(hq[1]));
                *(uint2*)(g_ow_hi + i) = make_uint2(h0, h1);
                *(uint2*)(g_ow_lo + i) = make_uint2(l0, l1);
            } else if (i < (size_t)NOUTW + NW1) {
                size_t k = i - NOUTW;
                float4 v = *(const float4*)(cvtW1 + k);
                *(uint2*)(g_w1s + k) = make_uint2(pack_half2(v.x, v.y), pack_half2(v.z, v.w));
            } else {
                size_t k = i - NOUTW - NW1;
                float4 v = *(const float4*)(cvtW2 + k);
                *(uint2*)(g_w2s + k) = make_uint2(pack_half2(v.x, v.y), pack_half2(v.z, v.w));
            }
        }
        return;
    }

    if (MODE == 1 && (int)blockIdx.y >= (M >> 7)) {
        // ---- fused rmsnorm2 + routing consumer (rides out-proj tail) ----
        int rb = ((int)blockIdx.y - (M >> 7)) * gridDim.x + blockIdx.x;  // 0..511
        int mb = rb >> 4;                                               // m-block this serves
        if (tid == 0) {
            while (atomicAdd(&g_obcnt[mb], 0) < (int)gridDim.x) __nanosleep(128);
        }
        __syncthreads();
        float* h2row = (float*)smem;     // 8KB of the dynamic smem
        __shared__ float red2[256];
        __shared__ float lg[NEXP];
        for (int ti = 0; ti < 8; ti++) {
            int n = rb * 8 + ti;
            const float* xr = C + (size_t)n * N;
            float s = 0.f;
            for (int k = tid * 4; k < EE; k += 1024) {
                float4 v = __ldcg((const float4*)(xr + k));
                s += v.x*v.x + v.y*v.y + v.z*v.z + v.w*v.w;
            }
            red2[tid] = s; __syncthreads();
            for (int o = 128; o; o >>= 1) { if (tid < o) red2[tid] += red2[tid + o]; __syncthreads(); }
            float r = rsqrtf(red2[0] * (1.0f / EE) + 1.1920929e-7f);
            for (int k = tid * 4; k < EE; k += 1024) {
                float4 v = __ldcg((const float4*)(xr + k));
                float f0 = v.x*r, f1 = v.y*r, f2 = v.z*r, f3 = v.w*r;   // norm2_w == handled below
                // apply weight (norm2_w passed via gwR+NEXP*EE? no — w applied here)
                f0 *= __ldg(gwR + NEXP*EE + k);     f1 *= __ldg(gwR + NEXP*EE + k + 1);
                f2 *= __ldg(gwR + NEXP*EE + k + 2); f3 *= __ldg(gwR + NEXP*EE + k + 3);
                *(float4*)(h2row + k) = make_float4(f0, f1, f2, f3);
                uint32_t h0 = pack_half2(f0, f1), h1 = pack_half2(f2, f3);
                *(uint2*)(ysR + (size_t)n*EE + k) = make_uint2(h0, h1);
            }
            __syncthreads();
            int wg = tid >> 5, lane = tid & 31;
            const float* gr = gwR + (size_t)wg * EE;
            float p = 0.f;
            for (int k = lane * 4; k < EE; k += 128) {
                float4 a = *(const float4*)(h2row + k);
                float4 g4 = *(const float4*)(gr + k);
                p += a.x*g4.x + a.y*g4.y + a.z*g4.z + a.w*g4.w;
            }
            for (int o = 16; o; o >>= 1) p += __shfl_xor_sync(0xffffffffu, p, o);
            if (!lane) lg[wg] = p;
            __syncthreads();
            if (tid == 0) {
                float mx = lg[0];
                #pragma unroll
                for (int e2 = 1; e2 < NEXP; e2++) mx = fmaxf(mx, lg[e2]);
                float ge[NEXP]; float sum = 0.f;
                #pragma unroll
                for (int e2 = 0; e2 < NEXP; e2++) { ge[e2] = __expf(lg[e2] - mx); sum += ge[e2]; }
                float inv = 1.f / sum;
                int i1 = 0; float v1 = -1.f;
                #pragma unroll
                for (int e2 = 0; e2 < NEXP; e2++) {
                    ge[e2] *= inv;
                    atomicAdd(&g_probs[e2], ge[e2]);
                    if (ge[e2] > v1) { v1 = ge[e2]; i1 = e2; }
                }
                int i2 = 0; float v2 = -2.f;
                #pragma unroll
                for (int e2 = 0; e2 < NEXP; e2++)
                    if (e2 != i1 && ge[e2] > v2) { v2 = ge[e2]; i2 = e2; }
                int s1 = atomicAdd(&g_cnt[i1], 1);
                g_idx[i1 * CAP + s1] = n; g_wgt[i1 * CAP + s1] = v1;
                int s2 = atomicAdd(&g_cnt[i2], 1);
                g_idx[i2 * CAP + s2] = n; g_wgt[i2 * CAP + s2] = v2;
            }
            __syncthreads();
        }
        return;
    }

    const int m0 = blockIdx.y * 128;
    const int n0 = blockIdx.x * 128;
    const int wid = tid >> 5;
    const int lid = tid & 31;
    const int wm = (wid >> 2) * 64;
    const int wn = (wid & 3) * 32;
    const int NC = K >> 5;

    auto load_chunk = [&](int kc, int bsel) {
        const uint32_t bb = SM_BUF + (uint32_t)bsel * BUFB;
        const int kofs = kc << 5;
        #pragma unroll
        for (int j = 0; j < 8; j++) {
            int idx = tid + 256 * j;
            int mat = idx >> 9;
            int ci  = idx & 511;
            int r   = ci >> 2;
            int c   = ci & 3;
            uint32_t dst = bb + mat * MATB + r * ROWB + c * 16;
            if (mat < 2) {
                const bf16* src = (mat == 0 ? Ahi : Alo) + (size_t)(m0 + r) * K + kofs + c * 8;
                cp16(dst, src);
            } else {
                const bf16* src = (mat == 2 ? Bhi : Blo) + (size_t)(n0 + r) * K + kofs + c * 8;
                cp16(dst, src);
            }
        }
        CP_COMMIT();
    };

    float acc[4][4][4];
    #pragma unroll
    for (int mt = 0; mt < 4; mt++)
        #pragma unroll
        for (int nt = 0; nt < 4; nt++)
            #pragma unroll
            for (int q = 0; q < 4; q++) acc[mt][nt][q] = 0.f;

    const uint32_t aoff = (uint32_t)((lid & 15) * ROWB + (lid >> 4) * 16);
    const uint32_t boff = (uint32_t)((((lid >> 4) << 3) + (lid & 7)) * ROWB + ((lid >> 3) & 1) * 16);

    load_chunk(0, 0);
    for (int kc = 0; kc < NC; kc++) {
        if (kc + 1 < NC) { load_chunk(kc + 1, (kc + 1) & 1); CP_WAIT(1); }
        else             { CP_WAIT(0); }
        __syncthreads();

        const uint32_t bb = SM_BUF + (uint32_t)(kc & 1) * BUFB;
        const uint32_t a_h = bb + wm * ROWB + aoff;
        const uint32_t a_l = a_h + MATB;
        const uint32_t b_h = bb + 2 * MATB + wn * ROWB + boff;
        const uint32_t b_l = b_h + MATB;

        #pragma unroll
        for (int ks = 0; ks < 2; ks++) {
            uint32_t ua[4][4], ub[4][2], vb[4][2];
            #pragma unroll
            for (int mt = 0; mt < 4; mt++)
                LDSM4(ua[mt][0], ua[mt][1], ua[mt][2], ua[mt][3], a_h + mt * (16 * ROWB) + ks * 32);
            #pragma unroll
            for (int bt = 0; bt < 2; bt++) {
                LDSM4(ub[2*bt][0], ub[2*bt][1], ub[2*bt+1][0], ub[2*bt+1][1], b_h + bt * (16 * ROWB) + ks * 32);
                LDSM4(vb[2*bt][0], vb[2*bt][1], vb[2*bt+1][0], vb[2*bt+1][1], b_l + bt * (16 * ROWB) + ks * 32);
            }
            #pragma unroll
            for (int mt = 0; mt < 4; mt++)
                #pragma unroll
                for (int nt = 0; nt < 4; nt++)
                    MMA16816(acc[mt][nt], ua[mt], ub[nt]);
            #pragma unroll
            for (int mt = 0; mt < 4; mt++)
                #pragma unroll
                for (int nt = 0; nt < 4; nt++)
                    MMA16816(acc[mt][nt], ua[mt], vb[nt]);
            #pragma unroll
            for (int mt = 0; mt < 4; mt++)
                LDSM4(ua[mt][0], ua[mt][1], ua[mt][2], ua[mt][3], a_l + mt * (16 * ROWB) + ks * 32);
            #pragma unroll
            for (int mt = 0; mt < 4; mt++)
                #pragma unroll
                for (int nt = 0; nt < 4; nt++)
                    MMA16816(acc[mt][nt], ua[mt], ub[nt]);
        }
        __syncthreads();
    }

    const int rbase = m0 + wm + (lid >> 2);
    const int cbase = n0 + wn + (lid & 3) * 2;
    #pragma unroll
    for (int mt = 0; mt < 4; mt++) {
        #pragma unroll
        for (int half = 0; half < 2; half++) {
            const int row = rbase + mt * 16 + half * 8;
            #pragma unroll
            for (int nt = 0; nt < 4; nt++) {
                const int col = cbase + nt * 8;
                const float d0 = acc[mt][nt][half * 2 + 0];
                const float d1 = acc[mt][nt][half * 2 + 1];
                if (MODE == 0) {
                    uint32_t h = pack_bf16x2(d0, d1);
                    bf16* hp = (bf16*)&h;
                    uint32_t l = pack_bf16x2(d0 - __bfloat162float(hp[0]), d1 - __bfloat162float(hp[1]));
                    *(uint32_t*)(Chi + (size_t)row * N + col) = h;
                    *(uint32_t*)(Clo + (size_t)row * N + col) = l;
                } else {
                    const float* rp = R + (size_t)row * N + col;
                    *(float2*)(C + (size_t)row * N + col) = make_float2(d0 + rp[0], d1 + rp[1]);
                }
            }
        }
    }
    if (MODE == 1) {
        __syncthreads();
        __threadfence();
        if (tid == 0) atomicAdd(&g_obcnt[blockIdx.y], 1);
    }
}

// ---------------- 1-pass fp16 GEMM (post-routing MoE only) ----------------
#define STG1B  (2*MATB)
#define GEMM1_SMEM (2*STG1B)

template<int MODE>
__global__ __launch_bounds__(256, 2)
void tc_gemm1(const __half* __restrict__ A, const __half* __restrict__ B,
              float* __restrict__ C, __half* __restrict__ Cs,
              int M, int N, int K) {
    extern __shared__ char smem[];
    const uint32_t SM_BUF = smem_to_u32(smem);

    const int e = blockIdx.z;
    const int Me = g_cnt[e];
    const int m0 = blockIdx.y * 128;
    const int n0 = blockIdx.x * 128;
    if (m0 >= Me) return;
    const int tid = threadIdx.x;
    const int wid = tid >> 5;
    const int lid = tid & 31;
    const int wm = (wid >> 2) * 64;
    const int wn = (wid & 3) * 32;

    const size_t bbase = (size_t)e * (size_t)N * K;
    const int NC = K >> 5;

    auto load_chunk = [&](int kc, int bsel) {
        const uint32_t bb = SM_BUF + (uint32_t)bsel * STG1B;
        const int kofs = kc << 5;
        #pragma unroll
        for (int j = 0; j < 4; j++) {
            int idx = tid + 256 * j;
            int mat = idx >> 9;
            int ci  = idx & 511;
            int r   = ci >> 2;
            int c   = ci & 3;
            uint32_t dst = bb + mat * MATB + r * ROWB + c * 16;
            if (mat == 0) {
                int rr = m0 + r; if (rr >= Me) rr = Me - 1;
                int arow = (MODE == 2) ? g_idx[e * CAP + rr] : (e * CAP + rr);
                cp16(dst, A + (size_t)arow * K + kofs + c * 8);
            } else {
                cp16(dst, B + bbase + (size_t)(n0 + r) * K + kofs + c * 8);
            }
        }
        CP_COMMIT();
    };

    float acc[4][4][4];
    #pragma unroll
    for (int mt = 0; mt < 4; mt++)
        #pragma unroll
        for (int nt = 0; nt < 4; nt++)
            #pragma unroll
            for (int q = 0; q < 4; q++) acc[mt][nt][q] = 0.f;

    const uint32_t aoff = (uint32_t)((lid & 15) * ROWB + (lid >> 4) * 16);
    const uint32_t boff = (uint32_t)((((lid >> 4) << 3) + (lid & 7)) * ROWB + ((lid >> 3) & 1) * 16);

    load_chunk(0, 0);
    for (int kc = 0; kc < NC; kc++) {
        if (kc + 1 < NC) { load_chunk(kc + 1, (kc + 1) & 1); CP_WAIT(1); }
        else             { CP_WAIT(0); }
        __syncthreads();

        const uint32_t bb = SM_BUF + (uint32_t)(kc & 1) * STG1B;
        const uint32_t a_s = bb + wm * ROWB + aoff;
        const uint32_t b_s = bb + MATB + wn * ROWB + boff;

        #pragma unroll
        for (int ks = 0; ks < 2; ks++) {
            uint32_t ua[4][4], ub[4][2];
            #pragma unroll
            for (int mt = 0; mt < 4; mt++)
                LDSM4(ua[mt][0], ua[mt][1], ua[mt][2], ua[mt][3], a_s + mt * (16 * ROWB) + ks * 32);
            #pragma unroll
            for (int bt = 0; bt < 2; bt++)
                LDSM4(ub[2*bt][0], ub[2*bt][1], ub[2*bt+1][0], ub[2*bt+1][1], b_s + bt * (16 * ROWB) + ks * 32);
            #pragma unroll
            for (int mt = 0; mt < 4; mt++)
                #pragma unroll
                for (int nt = 0; nt < 4; nt++)
                    MMAF16(acc[mt][nt], ua[mt], ub[nt]);
        }
        __syncthreads();
    }

    const int rbase = m0 + wm + (lid >> 2);
    const int cbase = n0 + wn + (lid & 3) * 2;
    #pragma unroll
    for (int mt = 0; mt < 4; mt++) {
        #pragma unroll
        for (int half = 0; half < 2; half++) {
            const int row = rbase + mt * 16 + half * 8;
            if (row >= Me) continue;
            int tok = 0; float wv = 0.f;
            if (MODE == 3) { tok = g_idx[e * CAP + row]; wv = g_wgt[e * CAP + row]; }
            #pragma unroll
            for (int nt = 0; nt < 4; nt++) {
                const int col = cbase + nt * 8;
                const float d0 = acc[mt][nt][half * 2 + 0];
                const float d1 = acc[mt][nt][half * 2 + 1];
                if (MODE == 2) {
                    float s0 = d0 / (1.f + __expf(-d0));
                    float s1 = d1 / (1.f + __expf(-d1));
                    *(uint32_t*)(Cs + ((size_t)e * CAP + row) * N + col) = pack_half2(s0, s1);
                } else {
                    red_add_v2(C + (size_t)tok * N + col, wv * d0, wv * d1);
                }
            }
        }
    }
}

// ---------------- tensor-core attention v2 ----------------
#define AROWB 272
#define AKROWS 32
#define AMATB (AKROWS*AROWB)
#define ABUFB (4*AMATB)
#define ATT_SMEM (2*ABUFB)

__global__ __launch_bounds__(128, 2)
void attn_tc_kernel(const bf16* __restrict__ qkvh, const bf16* __restrict__ qkvl,
                    const int* __restrict__ mask,
                    bf16* __restrict__ ohi, bf16* __restrict__ olo) {
    extern __shared__ char asmem[];
    const uint32_t SB = smem_to_u32(asmem);
    const int qt = (int)gridDim.x - 1 - (int)blockIdx.x;
    const int h  = blockIdx.y;
    const int b  = blockIdx.z;
    const int tid = threadIdx.x;
    const int wid = tid >> 5;
    const int lid = tid & 31;
    const int c2  = (lid & 3) * 2;
    const float isc = 0.08838834764831845f;

    const int tqA = qt * 64 + wid * 16 + (lid >> 2);
    const int tqB = tqA + 8;
    const int wrowmin = qt * 64 + wid * 16;
    const int tok = b * SS + h * 64 + (tqA >> 4);
    const size_t qb = (size_t)tok * QKVN;
    const int colA = (tqA & 15) << 7;
    const int colB = (tqB & 15) << 7;

    uint32_t qa_h[8][4], qa_l[8][4];
    #pragma unroll
    for (int ks = 0; ks < 8; ks++) {
        int k0 = ks * 16 + c2;
        qa_h[ks][0] = *(const uint32_t*)(qkvh + qb + colA + k0);
        qa_h[ks][1] = *(const uint32_t*)(qkvh + qb + colB + k0);
        qa_h[ks][2] = *(const uint32_t*)(qkvh + qb + colA + k0 + 8);
        qa_h[ks][3] = *(const uint32_t*)(qkvh + qb + colB + k0 + 8);
        qa_l[ks][0] = *(const uint32_t*)(qkvl + qb + colA + k0);
        qa_l[ks][1] = *(const uint32_t*)(qkvl + qb + colB + k0);
        qa_l[ks][2] = *(const uint32_t*)(qkvl + qb + colA + k0 + 8);
        qa_l[ks][3] = *(const uint32_t*)(qkvl + qb + colB + k0 + 8);
    }

    float o[16][4];
    #pragma unroll
    for (int dt = 0; dt < 16; dt++)
        #pragma unroll
        for (int q = 0; q < 4; q++) o[dt][q] = 0.f;
    float mA = -1e30f, lA = 0.f, mB = -1e30f, lB = 0.f;

    const int KT = 2 * qt + 2;

    auto load_kv = [&](int kt, int bsel) {
        const uint32_t bb = SB + (uint32_t)bsel * ABUFB;
        #pragma unroll
        for (int j = 0; j < 16; j++) {
            int idx = tid + 128 * j;
            int mat = idx >> 9;
            int ci  = idx & 511;
            int r   = ci >> 4;
            int c   = ci & 15;
            int t   = kt * AKROWS + r;
            size_t src = ((size_t)(b * SS + h * 64 + (t >> 4))) * QKVN
                       + ((t & 15) << 7) + ((mat < 2) ? 2048 : 4096) + c * 8;
            const bf16* sp = ((mat & 1) ? qkvl : qkvh) + src;
            cp16(bb + mat * AMATB + r * AROWB + c * 16, sp);
        }
        CP_COMMIT();
    };

    const uint32_t koff = (uint32_t)((((lid >> 4) << 3) + (lid & 7)) * AROWB + ((lid >> 3) & 1) * 16);
    const uint32_t voff = (uint32_t)((((lid >> 3) & 1) * 8 + (lid & 7)) * AROWB + (lid >> 4) * 16);

    load_kv(0, 0);
    for (int kt = 0; kt < KT; kt++) {
        if (kt + 1 < KT) { load_kv(kt + 1, (kt + 1) & 1); CP_WAIT(1); }
        else             { CP_WAIT(0); }
        __syncthreads();
        const uint32_t bb = SB + (uint32_t)(kt & 1) * ABUFB;
        const uint32_t Kh = bb, Kl = bb + AMATB, Vh = bb + 2 * AMATB, Vl = bb + 3 * AMATB;

        float s[4][4];
        #pragma unroll
        for (int nt = 0; nt < 4; nt++)
            #pragma unroll
            for (int q = 0; q < 4; q++) s[nt][q] = 0.f;

        #pragma unroll
        for (int ks = 0; ks < 8; ks++) {
            #pragma unroll
            for (int g = 0; g < 2; g++) {
                uint32_t kh[4], kl[4];
                LDSM4(kh[0], kh[1], kh[2], kh[3], Kh + g * (16 * AROWB) + koff + ks * 32);
                LDSM4(kl[0], kl[1], kl[2], kl[3], Kl + g * (16 * AROWB) + koff + ks * 32);
                uint32_t bh0[2] = {kh[0], kh[1]}, bh1[2] = {kh[2], kh[3]};
                uint32_t bl0[2] = {kl[0], kl[1]}, bl1[2] = {kl[2], kl[3]};
                MMA16816(s[2*g],   qa_h[ks], bh0);
                MMA16816(s[2*g+1], qa_h[ks], bh1);
                MMA16816(s[2*g],   qa_h[ks], bl0);
                MMA16816(s[2*g+1], qa_h[ks], bl1);
                MMA16816(s[2*g],   qa_l[ks], bh0);
                MMA16816(s[2*g+1], qa_l[ks], bh1);
            }
        }

        const int tk0 = kt * AKROWS;
        const bool fullcausal = (tk0 + AKROWS - 1) <= wrowmin;
        #pragma unroll
        for (int nt = 0; nt < 4; nt++) {
            int t0 = tk0 + nt * 8 + c2;
            int2 mv = *(const int2*)(mask + b * SS + t0);
            #pragma unroll
            for (int q = 0; q < 4; q++) {
                float v = s[nt][q] * isc;
                if (((q & 1) ? mv.y : mv.x) == 0) v = NEGV;
                if (fullcausal) {
                    v += 1.0f;
                } else {
                    int t = t0 + (q & 1);
                    int row = (q < 2) ? tqA : tqB;
                    v += (t <= row) ? 1.0f : NEGV;
                }
                s[nt][q] = v;
            }
        }

        float mxA = -1e30f, mxB = -1e30f;
        #pragma unroll
        for (int nt = 0; nt < 4; nt++) {
            mxA = fmaxf(mxA, fmaxf(s[nt][0], s[nt][1]));
            mxB = fmaxf(mxB, fmaxf(s[nt][2], s[nt][3]));
        }
        mxA = fmaxf(mxA, __shfl_xor_sync(0xffffffffu, mxA, 1));
        mxA = fmaxf(mxA, __shfl_xor_sync(0xffffffffu, mxA, 2));
        mxB = fmaxf(mxB, __shfl_xor_sync(0xffffffffu, mxB, 1));
        mxB = fmaxf(mxB, __shfl_xor_sync(0xffffffffu, mxB, 2));
        float mnA = fmaxf(mA, mxA), mnB = fmaxf(mB, mxB);
        float sumA = 0.f, sumB = 0.f;
        #pragma unroll
        for (int nt = 0; nt < 4; nt++) {
            s[nt][0] = __expf(s[nt][0] - mnA);
            s[nt][1] = __expf(s[nt][1] - mnA);
            s[nt][2] = __expf(s[nt][2] - mnB);
            s[nt][3] = __expf(s[nt][3] - mnB);
            sumA += s[nt][0] + s[nt][1];
            sumB += s[nt][2] + s[nt][3];
        }
        sumA += __shfl_xor_sync(0xffffffffu, sumA, 1);
        sumA += __shfl_xor_sync(0xffffffffu, sumA, 2);
        sumB += __shfl_xor_sync(0xffffffffu, sumB, 1);
        sumB += __shfl_xor_sync(0xffffffffu, sumB, 2);
        float aA = __expf(mA - mnA), aB = __expf(mB - mnB);
        lA = lA * aA + sumA;  mA = mnA;
        lB = lB * aB + sumB;  mB = mnB;
        #pragma unroll
        for (int dt = 0; dt < 16; dt++) {
            o[dt][0] *= aA; o[dt][1] *= aA;
            o[dt][2] *= aB; o[dt][3] *= aB;
        }

        #pragma unroll
        for (int ks2 = 0; ks2 < 2; ks2++) {
            uint32_t pa_h[4], pa_l[4];
            {
                float* p0 = s[2*ks2]; float* p1 = s[2*ks2+1];
                pa_h[0] = pack_bf16x2(p0[0], p0[1]);
                pa_h[1] = pack_bf16x2(p0[2], p0[3]);
                pa_h[2] = pack_bf16x2(p1[0], p1[1]);
                pa_h[3] = pack_bf16x2(p1[2], p1[3]);
                bf16* t0 = (bf16*)&pa_h[0]; bf16* t1 = (bf16*)&pa_h[1];
                bf16* t2 = (bf16*)&pa_h[2]; bf16* t3 = (bf16*)&pa_h[3];
                pa_l[0] = pack_bf16x2(p0[0]-__bfloat162float(t0[0]), p0[1]-__bfloat162float(t0[1]));
                pa_l[1] = pack_bf16x2(p0[2]-__bfloat162float(t1[0]), p0[3]-__bfloat162float(t1[1]));
                pa_l[2] = pack_bf16x2(p1[0]-__bfloat162float(t2[0]), p1[1]-__bfloat162float(t2[1]));
                pa_l[3] = pack_bf16x2(p1[2]-__bfloat162float(t3[0]), p1[3]-__bfloat162float(t3[1]));
            }
            #pragma unroll
            for (int db = 0; db < 8; db++) {
                uint32_t vh[4], vl[4];
                LDSM4T(vh[0], vh[1], vh[2], vh[3], Vh + ks2 * (16 * AROWB) + db * 32 + voff);
                LDSM4T(vl[0], vl[1], vl[2], vl[3], Vl + ks2 * (16 * AROWB) + db * 32 + voff);
                uint32_t bh0[2] = {vh[0], vh[1]}, bh1[2] = {vh[2], vh[3]};
                uint32_t bl0[2] = {vl[0], vl[1]}, bl1[2] = {vl[2], vl[3]};
                MMA16816(o[2*db],   pa_h, bh0);
                MMA16816(o[2*db+1], pa_h, bh1);
                MMA16816(o[2*db],   pa_h, bl0);
                MMA16816(o[2*db+1], pa_h, bl1);
                MMA16816(o[2*db],   pa_l, bh0);
                MMA16816(o[2*db+1], pa_l, bh1);
            }
        }
        __syncthreads();
    }

    const float ivA = 1.f / lA, ivB = 1.f / lB;
    const size_t obase = (size_t)tok * EE;
    #pragma unroll
    for (int dt = 0; dt < 16; dt++) {
        int d = dt * 8 + c2;
        float a0 = o[dt][0] * ivA, a1 = o[dt][1] * ivA;
        float b0 = o[dt][2] * ivB, b1 = o[dt][3] * ivB;
        uint32_t hA = pack_bf16x2(a0, a1);
        bf16* tp = (bf16*)&hA;
        uint32_t lA2 = pack_bf16x2(a0 - __bfloat162float(tp[0]), a1 - __bfloat162float(tp[1]));
        *(uint32_t*)(ohi + obase + colA + d) = hA;
        *(uint32_t*)(olo + obase + colA + d) = lA2;
        uint32_t hB = pack_bf16x2(b0, b1);
        bf16* tq2 = (bf16*)&hB;
        uint32_t lB2 = pack_bf16x2(b0 - __bfloat162float(tq2[0]), b1 - __bfloat162float(tq2[1]));
        *(uint32_t*)(ohi + obase + colB + d) = hB;
        *(uint32_t*)(olo + obase + colB + d) = lB2;
    }
}

__global__ void loss_kernel(float* __restrict__ out, int lossidx) {
    if (threadIdx.x == 0) {
        float pr[NEXP]; float mean = 0.f;
        #pragma unroll
        for (int e = 0; e < NEXP; e++) { pr[e] = g_probs[e] * (1.0f / NTOK); mean += pr[e]; }
        mean *= (1.0f / NEXP);
        float var = 0.f;
        #pragma unroll
        for (int e = 0; e < NEXP; e++) { float d = pr[e] - mean; var += d * d; }
        var *= (1.0f / NEXP);
        out[lossidx] = var / (mean * mean + 1e-10f);
    }
}

// ---------------- launch ----------------
// NOTE: the route consumer expects gwR to point at a buffer where
// [0, NEXP*EE) = gate_W and [NEXP*EE, NEXP*EE+EE) = norm2_w. gate_W and
// norm2_w are separate harness buffers, so we pass gate_W and read norm2_w
// via a second pointer baked in through cvtW2 slot when MODE==1? No — we
// keep it simple: stage norm2_w copied after a device gate copy.
__device__ float g_gate_n2[NEXP*EE + EE];

__global__ __launch_bounds__(256)
void gatecopy_kernel(const float* __restrict__ gw, const float* __restrict__ n2w) {
    int i = blockIdx.x * 256 + threadIdx.x;
    if (i < NEXP * EE) g_gate_n2[i] = gw[i];
    if (i < EE) g_gate_n2[NEXP * EE + i] = n2w[i];
}

extern "C" void kernel_launch(void* const* d_in, const int* in_sizes, int n_in,
                              void* d_out, int out_size) {
    const float* x     = (const float*)d_in[0];
    const int*   mask  = (const int*)  d_in[1];
    const float* n1w   = (const float*)d_in[2];
    const float* qkvW  = (const float*)d_in[3];
    const float* outW  = (const float*)d_in[4];
    const float* n2w   = (const float*)d_in[5];
    const float* gateW = (const float*)d_in[6];
    const float* W1    = (const float*)d_in[7];
    const float* W2    = (const float*)d_in[8];
    float* out = (float*)d_out;

    bf16 *phh, *phl, *pqvh, *pqvl, *path, *patl;
    __half *ph2s, *phx, *pw1s, *pw2s;
    bf16 *pqwh, *pqwl, *powh, *powl;
    float* pgate;
    cudaGetSymbolAddress((void**)&phh,  g_h_hi);  cudaGetSymbolAddress((void**)&phl,  g_h_lo);
    cudaGetSymbolAddress((void**)&pqvh, g_qkvh);  cudaGetSymbolAddress((void**)&pqvl, g_qkvl);
    cudaGetSymbolAddress((void**)&path, g_at_hi); cudaGetSymbolAddress((void**)&patl, g_at_lo);
    cudaGetSymbolAddress((void**)&ph2s, g_h2s);
    cudaGetSymbolAddress((void**)&phx,  g_hx);
    cudaGetSymbolAddress((void**)&pqwh, g_qw_hi); cudaGetSymbolAddress((void**)&pqwl, g_qw_lo);
    cudaGetSymbolAddress((void**)&powh, g_ow_hi); cudaGetSymbolAddress((void**)&powl, g_ow_lo);
    cudaGetSymbolAddress((void**)&pw1s, g_w1s);
    cudaGetSymbolAddress((void**)&pw2s, g_w2s);
    cudaGetSymbolAddress((void**)&pgate, g_gate_n2);

    cudaFuncSetAttribute(tc_gemm<0>, cudaFuncAttributeMaxDynamicSharedMemorySize, GEMM_SMEM);
    cudaFuncSetAttribute(tc_gemm<1>, cudaFuncAttributeMaxDynamicSharedMemorySize, GEMM_SMEM);
    cudaFuncSetAttribute(tc_gemm1<2>, cudaFuncAttributeMaxDynamicSharedMemorySize, GEMM1_SMEM);
    cudaFuncSetAttribute(tc_gemm1<3>, cudaFuncAttributeMaxDynamicSharedMemorySize, GEMM1_SMEM);
    cudaFuncSetAttribute(attn_tc_kernel, cudaFuncAttributeMaxDynamicSharedMemorySize, ATT_SMEM);

    gatecopy_kernel<<<(NEXP * EE + 255) / 256, 256>>>(gateW, n2w);
    rmsnorm_kernel<<<NTOK + QCVB, 256>>>(x, n1w, phh, phl, qkvW);
    tc_gemm<0><<<dim3(QKVN / 128, NTOK / 128 + RCVY), 256, GEMM_SMEM>>>(
        phh, phl, pqwh, pqwl, nullptr, nullptr, pqvh, pqvl,
        NTOK, QKVN, EE, outW, W1, W2, nullptr, nullptr);
    attn_tc_kernel<<<dim3(SS / 64, NH, NB), 128, ATT_SMEM>>>(pqvh, pqvl, mask, path, patl);
    // out-proj (x1 -> out) + fused rmsnorm2/routing consumers in the tail
    tc_gemm<1><<<dim3(EE / 128, NTOK / 128 + ROUTEY), 256, GEMM_SMEM>>>(
        path, patl, powh, powl, out, x, nullptr, nullptr,
        NTOK, EE, EE, nullptr, nullptr, nullptr, pgate, ph2s);
    if (out_size > NTOK * EE)
        loss_kernel<<<1, 32>>>(out, out_size - 1);
    tc_gemm1<2><<<dim3(EXPH / 128, CAP / 128, NEXP), 256, GEMM1_SMEM>>>(
        ph2s, pw1s, nullptr, phx, CAP, EXPH, EE);
    tc_gemm1<3><<<dim3(EE / 128, CAP / 128, NEXP), 256, GEMM1_SMEM>>>(
        phx, pw2s, out, nullptr, CAP, EE, EXPH);
}